// round 12
// baseline (speedup 1.0000x reference)
#include <cuda_runtime.h>
#include <cstdint>

// TaylorExp: x [4,16,4096,16] f32 -> out [4,16,4096,273] f32
// out_row = [1, 0.5*x, vec(x x^T) / (4*sqrt(2))]
//
// R11: R10 (constexpr table copy + table-driven decode + STG.128
// st.global.cs evict-first streaming stores) with __launch_bounds__(256, 8)
// to force regs<=32 -> 8 CTAs/SM -> full occupancy for deeper store queues.

#define WARPS_PER_BLOCK 8
#define THREADS (WARPS_PER_BLOCK * 32)

static constexpr int TOTAL_ROWS  = 4 * 16 * 4096;   // 262144
static constexpr int GROUPS      = TOTAL_ROWS / 4;  // 65536 (4 rows per warp)
static constexpr int VEC_PER_GRP = 273;             // float4 per group

// ---- compile-time offset table ----------------------------------------
struct TabInit {
    unsigned w[VEC_PER_GRP * 4];
    constexpr TabInit() : w() {
        for (int ec = 0; ec < VEC_PER_GRP * 4; ++ec) {
            const int row = ec / 273;
            const int f   = ec - row * 273;
            int ia = 0, ib = 0;
            if (f == 0)       { ia = row * 17;          ib = 68 + row * 17; }
            else if (f <= 16) { ia = row * 17 + f;      ib = 68 + row * 17; }
            else {
                const int q = f - 17;
                ia = row * 17 + 1 + (q >> 4);
                ib = 68 + row * 17 + 1 + (q & 15);
            }
            w[ec] = (unsigned)(ia * 4) | ((unsigned)(ib * 4) << 16);
        }
    }
};
__device__ const TabInit g_tab = TabInit();

__device__ __forceinline__ float lds_f32(unsigned addr) {
    float v;
    asm volatile("ld.shared.f32 %0, [%1];" : "=f"(v) : "r"(addr));
    return v;
}

__device__ __forceinline__ void stg_cs_v4(float4* p, float4 v) {
    asm volatile("st.global.cs.v4.f32 [%0], {%1, %2, %3, %4};"
                 :: "l"(p), "f"(v.x), "f"(v.y), "f"(v.z), "f"(v.w)
                 : "memory");
}

__global__ __launch_bounds__(THREADS, 8)
void TaylorExp_14783277432863_kernel(const float* __restrict__ x,
                                     float* __restrict__ out) {
    __shared__ uint4 tab[VEC_PER_GRP];             // 4368 B, block-shared
    __shared__ float pq[WARPS_PER_BLOCK][136];     // P[68] | Q[68] per warp

    const int tid  = threadIdx.x;
    const int warp = tid >> 5;
    const int lane = tid & 31;
    const int group = blockIdx.x * WARPS_PER_BLOCK + warp;   // grid exact

    // ---- copy precomputed table to shared (straight-line, no branches) ----
    const uint4* gt = reinterpret_cast<const uint4*>(g_tab.w);
    tab[tid] = __ldg(&gt[tid]);                    // tid 0..255
    if (tid < VEC_PER_GRP - THREADS)               // 17 tail entries
        tab[THREADS + tid] = __ldg(&gt[THREADS + tid]);

    // ---- fill per-warp P/Q (pre-scaled inputs) ----
    const float4* xg = reinterpret_cast<const float4*>(x) + (size_t)group * 16;
    if (lane < 16) {
        float4 v = __ldg(&xg[lane]);
        const int row = lane >> 2, part = lane & 3;
        float* P = pq[warp];
        float* Q = pq[warp] + 68;
        const int bi = row * 17 + 1 + part * 4;
        P[bi + 0] = 0.5f * v.x;  P[bi + 1] = 0.5f * v.y;
        P[bi + 2] = 0.5f * v.z;  P[bi + 3] = 0.5f * v.w;
        const float c2 = 0.5f * 0.70710678118654752f;   // 0.5/sqrt(2)
        Q[bi + 0] = c2 * v.x;    Q[bi + 1] = c2 * v.y;
        Q[bi + 2] = c2 * v.z;    Q[bi + 3] = c2 * v.w;
    }
    if (lane < 4) {                          // unit entries for const/linear
        pq[warp][lane * 17]      = 1.0f;
        pq[warp][68 + lane * 17] = 1.0f;
    }
    __syncthreads();

    const unsigned sb = (unsigned)__cvta_generic_to_shared(&pq[warp][0]);
    float4* og = reinterpret_cast<float4*>(out) + (size_t)group * VEC_PER_GRP;

    #pragma unroll
    for (int it = 0; it < 9; ++it) {
        const int k = lane + it * 32;
        if (it < 8 || k < VEC_PER_GRP) {     // 273 = 8*32 + 17
            const uint4 cd = tab[k];
            float4 v;
            v.x = lds_f32(sb + (cd.x & 0xFFFFu)) * lds_f32(sb + (cd.x >> 16));
            v.y = lds_f32(sb + (cd.y & 0xFFFFu)) * lds_f32(sb + (cd.y >> 16));
            v.z = lds_f32(sb + (cd.z & 0xFFFFu)) * lds_f32(sb + (cd.z >> 16));
            v.w = lds_f32(sb + (cd.w & 0xFFFFu)) * lds_f32(sb + (cd.w >> 16));
            stg_cs_v4(og + k, v);            // evict-first streaming store
        }
    }
}

extern "C" void kernel_launch(void* const* d_in, const int* in_sizes, int n_in,
                              void* d_out, int out_size) {
    const float* x = (const float*)d_in[0];
    float* out = (float*)d_out;
    (void)in_sizes; (void)n_in; (void)out_size;

    const int blocks = GROUPS / WARPS_PER_BLOCK;   // 8192
    TaylorExp_14783277432863_kernel<<<blocks, THREADS>>>(x, out);
}